// round 11
// baseline (speedup 1.0000x reference)
#include <cuda_runtime.h>

#define CH 64
#define MAXN 65536
#define MAXDEG 64

// Scratch (no allocs allowed).
__device__ int   g_deg[MAXN];
__device__ int   g_bucket[(size_t)MAXN * MAXDEG];
__device__ float g_colsum[CH];
__device__ float g_sumsq[CH];
__device__ int   g_idx64;

#define FFMA2(acc, a, b) \
    asm("fma.rn.f32x2 %0, %1, %2, %0;" : "+l"(acc) : "l"(a), "l"(b))
#define PACK2(out, lo, hi) \
    asm("mov.b64 %0, {%1, %2};" : "=l"(out) : "f"(lo), "f"(hi))
#define UNPACK2(lo, hi, in) \
    asm("mov.b64 {%0, %1}, %2;" : "=f"(lo), "=f"(hi) : "l"(in))

// ---------------------------------------------------------------------------
// K1: detect index dtype (parallel ballot) + zero reduction buffers.
// ---------------------------------------------------------------------------
__global__ void k_detect(const int* __restrict__ ei32, int E) {
    int t = threadIdx.x;
    int cnt = (E < 64) ? E : 64;
    int hi = (t < cnt) ? ei32[2 * t + 1] : 0;
    // int64 edge_index => high 32-bit word of every entry is 0.
    unsigned m0 = __ballot_sync(0xffffffffu, hi != 0);
    __shared__ unsigned sm[2];
    if ((t & 31) == 0) sm[t >> 5] = m0;
    __syncthreads();
    if (t == 0) g_idx64 = ((sm[0] | sm[1]) == 0u) ? 1 : 0;
    if (t < CH) { g_colsum[t] = 0.f; g_sumsq[t] = 0.f; }
}

// ---------------------------------------------------------------------------
// K2: zero degree counters.
// ---------------------------------------------------------------------------
__global__ void k_zero(int N) {
    int i = blockIdx.x * blockDim.x + threadIdx.x;
    if (i < N) g_deg[i] = 0;
}

// ---------------------------------------------------------------------------
// K3: single-pass bucket scatter; slot = atomic return value.
// ---------------------------------------------------------------------------
__global__ void k_bucket(const void* __restrict__ ei, int E) {
    const int idx64 = g_idx64;
    const long long* e64 = (const long long*)ei;
    const int*       e32 = (const int*)ei;
    int i = blockIdx.x * blockDim.x + threadIdx.x;
    if (i < E) {
        int src, dst;
        if (idx64) { src = (int)e64[i]; dst = (int)e64[E + i]; }
        else       { src = e32[i];      dst = e32[E + i]; }
        int slot = atomicAdd(&g_deg[dst], 1);
        if (slot < MAXDEG)
            g_bucket[(size_t)dst * MAXDEG + slot] = src;
    }
}

// ---------------------------------------------------------------------------
// Pair-packed 64x64 GEMM: h pairs pre-packed in smem (float2 per channel),
// hot loop = LDS + 8 weight-dup packs + 32 FFMA2 per kk (no h packs).
// ---------------------------------------------------------------------------
__device__ __forceinline__ void gemm64_pairs(
    const float4* __restrict__ wa, const float4* __restrict__ wb,
    const float2 (*__restrict__ hp)[CH], float* a0, float* a1) {
    unsigned long long pa[4][2];
    #pragma unroll
    for (int p = 0; p < 4; p++) { pa[p][0] = 0ull; pa[p][1] = 0ull; }
    #pragma unroll
    for (int kk = 0; kk < 16; kk++) {
        float4 va = wa[kk];
        float4 vb = wb[kk];
        unsigned long long wax, way, waz, waw, wbx, wby, wbz, wbw;
        PACK2(wax, va.x, va.x); PACK2(way, va.y, va.y);
        PACK2(waz, va.z, va.z); PACK2(waw, va.w, va.w);
        PACK2(wbx, vb.x, vb.x); PACK2(wby, vb.y, vb.y);
        PACK2(wbz, vb.z, vb.z); PACK2(wbw, vb.w, vb.w);
        #pragma unroll
        for (int p = 0; p < 4; p++) {
            const ulonglong2* hq = reinterpret_cast<const ulonglong2*>(hp[p]);
            ulonglong2 q0 = hq[2 * kk];          // channels 4kk, 4kk+1 (paired)
            ulonglong2 q1 = hq[2 * kk + 1];      // channels 4kk+2, 4kk+3
            FFMA2(pa[p][0], q0.x, wax); FFMA2(pa[p][0], q0.y, way);
            FFMA2(pa[p][0], q1.x, waz); FFMA2(pa[p][0], q1.y, waw);
            FFMA2(pa[p][1], q0.x, wbx); FFMA2(pa[p][1], q0.y, wby);
            FFMA2(pa[p][1], q1.x, wbz); FFMA2(pa[p][1], q1.y, wbw);
        }
    }
    #pragma unroll
    for (int p = 0; p < 4; p++) {
        UNPACK2(a0[2 * p], a0[2 * p + 1], pa[p][0]);
        UNPACK2(a1[2 * p], a1[2 * p + 1], pa[p][1]);
    }
}

// ---------------------------------------------------------------------------
// K4: fused gather + MLP + GraphNorm partial sums. Warp handles 8 rows
// (4 row-pairs), pair-packed staging. launch_bounds(256,4): force <=64 regs
// so 4 CTAs/SM are resident (was 3 at 68 regs) — issue-bound kernel.
// ---------------------------------------------------------------------------
__global__ void __launch_bounds__(256, 4)
k_mlp(const float* __restrict__ x,
      const float* __restrict__ W0, const float* __restrict__ ln0w,
      const float* __restrict__ ln0b, const float* __restrict__ W1,
      const float* __restrict__ ln1w, const float* __restrict__ ln1b,
      float* __restrict__ out, int N) {
    __shared__ __align__(16) float sW0[CH][68];
    __shared__ __align__(16) float sW1[CH][68];
    __shared__ __align__(16) float2 hp[8][4][CH];   // [warp][pair][channel]
    __shared__ float bsum[CH];
    __shared__ float bss[CH];

    const int tid  = threadIdx.x;
    const int lane = tid & 31;
    const int warp = tid >> 5;

    for (int i = tid; i < CH * CH; i += blockDim.x) {
        sW0[i >> 6][i & 63] = W0[i];
        sW1[i >> 6][i & 63] = W1[i];
    }
    if (tid < CH) { bsum[tid] = 0.f; bss[tid] = 0.f; }
    #pragma unroll
    for (int p = 0; p < 4; p++) {
        hp[warp][p][lane]      = make_float2(0.f, 0.f);
        hp[warp][p][lane + 32] = make_float2(0.f, 0.f);
    }

    const float w0a = ln0w[lane], w0b = ln0w[lane + 32];
    const float b0a = ln0b[lane], b0b = ln0b[lane + 32];
    const float w1a = ln1w[lane], w1b = ln1w[lane + 32];
    const float b1a = ln1b[lane], b1b = ln1b[lane + 32];
    __syncthreads();

    const float4* wa0 = reinterpret_cast<const float4*>(&sW0[lane][0]);
    const float4* wb0 = reinterpret_cast<const float4*>(&sW0[lane + 32][0]);
    const float4* wa1 = reinterpret_cast<const float4*>(&sW1[lane][0]);
    const float4* wb1 = reinterpret_cast<const float4*>(&sW1[lane + 32][0]);
    const float2* x2  = reinterpret_cast<const float2*>(x);

    float cs0 = 0.f, cs1 = 0.f, ss0 = 0.f, ss1 = 0.f;

    const int gwarp  = blockIdx.x * 8 + warp;
    const int nwarps = gridDim.x * 8;

    for (int base = gwarp * 8; base < N; base += nwarps * 8) {
        // ---- gather: h = x[row] + sum of neighbor rows, 4 parallel chains.
        //      lane holds channels (2l, 2l+1); write into pair-packed slots.
        #pragma unroll
        for (int r = 0; r < 8; r++) {
            int row = base + r;
            if (row < N) {
                int deg = g_deg[row];
                if (deg > MAXDEG) deg = MAXDEG;
                const int* nb = g_bucket + (size_t)row * MAXDEG;
                float2 acc0 = x2[row * 32 + lane];
                float2 acc1 = make_float2(0.f, 0.f);
                float2 acc2 = make_float2(0.f, 0.f);
                float2 acc3 = make_float2(0.f, 0.f);
                int j = 0;
                for (; j + 4 <= deg; j += 4) {
                    int s0 = nb[j];
                    int s1 = nb[j + 1];
                    int s2 = nb[j + 2];
                    int s3 = nb[j + 3];
                    float2 v0 = x2[s0 * 32 + lane];
                    float2 v1 = x2[s1 * 32 + lane];
                    float2 v2 = x2[s2 * 32 + lane];
                    float2 v3 = x2[s3 * 32 + lane];
                    acc0.x += v0.x; acc0.y += v0.y;
                    acc1.x += v1.x; acc1.y += v1.y;
                    acc2.x += v2.x; acc2.y += v2.y;
                    acc3.x += v3.x; acc3.y += v3.y;
                }
                for (; j < deg; j++) {
                    int s0 = nb[j];
                    float2 v0 = x2[s0 * 32 + lane];
                    acc0.x += v0.x; acc0.y += v0.y;
                }
                acc0.x += acc1.x; acc0.y += acc1.y;
                acc2.x += acc3.x; acc2.y += acc3.y;
                acc0.x += acc2.x; acc0.y += acc2.y;
                float* hpf = reinterpret_cast<float*>(&hp[warp][r >> 1][0]);
                int half = r & 1;
                hpf[4 * lane + half]     = acc0.x;   // channel 2*lane
                hpf[4 * lane + 2 + half] = acc0.y;   // channel 2*lane+1
            }
        }
        __syncwarp();

        // ---- layer 0 GEMM ----
        float a0[8], a1[8];
        gemm64_pairs(wa0, wb0, hp[warp], a0, a1);
        __syncwarp();

        // ---- LayerNorm 0 + ReLU, restage pair-packed ----
        #pragma unroll
        for (int r = 0; r < 8; r++) {
            float s = a0[r] + a1[r];
            #pragma unroll
            for (int o = 16; o; o >>= 1) s += __shfl_xor_sync(0xffffffffu, s, o);
            float mu = s * (1.f / 64.f);
            float d0 = a0[r] - mu, d1 = a1[r] - mu;
            float q = d0 * d0 + d1 * d1;
            #pragma unroll
            for (int o = 16; o; o >>= 1) q += __shfl_xor_sync(0xffffffffu, q, o);
            float inv = rsqrtf(q * (1.f / 64.f) + 1e-5f);
            float* hpf = reinterpret_cast<float*>(&hp[warp][r >> 1][0]);
            int half = r & 1;
            hpf[2 * lane + half]        = fmaxf(fmaf(d0 * inv, w0a, b0a), 0.f);
            hpf[2 * (lane + 32) + half] = fmaxf(fmaf(d1 * inv, w0b, b0b), 0.f);
        }
        __syncwarp();

        // ---- layer 1 GEMM ----
        gemm64_pairs(wa1, wb1, hp[warp], a0, a1);

        // ---- LayerNorm 1 + ReLU + store + GraphNorm partials ----
        #pragma unroll
        for (int r = 0; r < 8; r++) {
            int row = base + r;
            float s = a0[r] + a1[r];
            #pragma unroll
            for (int o = 16; o; o >>= 1) s += __shfl_xor_sync(0xffffffffu, s, o);
            float mu = s * (1.f / 64.f);
            float d0 = a0[r] - mu, d1 = a1[r] - mu;
            float q = d0 * d0 + d1 * d1;
            #pragma unroll
            for (int o = 16; o; o >>= 1) q += __shfl_xor_sync(0xffffffffu, q, o);
            float inv = rsqrtf(q * (1.f / 64.f) + 1e-5f);
            float v0 = fmaxf(fmaf(d0 * inv, w1a, b1a), 0.f);
            float v1 = fmaxf(fmaf(d1 * inv, w1b, b1b), 0.f);
            if (row < N) {
                float* orow = out + (size_t)row * CH;
                orow[lane]      = v0;
                orow[lane + 32] = v1;
                cs0 += v0; cs1 += v1;
                ss0 = fmaf(v0, v0, ss0);
                ss1 = fmaf(v1, v1, ss1);
            }
        }
        __syncwarp();
    }

    // column sum / sumsq partials: register -> shared -> 128 global atomics.
    atomicAdd(&bsum[lane], cs0);
    atomicAdd(&bsum[lane + 32], cs1);
    atomicAdd(&bss[lane], ss0);
    atomicAdd(&bss[lane + 32], ss1);
    __syncthreads();
    if (tid < CH) {
        atomicAdd(&g_colsum[tid], bsum[tid]);
        atomicAdd(&g_sumsq[tid],  bss[tid]);
    }
}

// ---------------------------------------------------------------------------
// K5: final GraphNorm, in-place, float4. var = E[h^2] - 2*am*mu + am^2.
// ---------------------------------------------------------------------------
__global__ void k_final(const float* __restrict__ gnw, const float* __restrict__ gnb,
                        const float* __restrict__ gna, float* __restrict__ out,
                        int N) {
    const float invN = 1.f / (float)N;
    const int t = blockIdx.x * blockDim.x + threadIdx.x;
    const int c0 = (t & 15) * 4;
    float am[4], w[4], b[4];
    #pragma unroll
    for (int j = 0; j < 4; j++) {
        int c = c0 + j;
        float mu  = g_colsum[c] * invN;
        float a   = gna[c] * mu;
        float ex2 = g_sumsq[c] * invN;
        float var = ex2 - 2.f * a * mu + a * a;
        am[j] = a;
        w[j]  = gnw[c] * rsqrtf(var + 1e-5f);
        b[j]  = gnb[c];
    }
    float4* o4 = reinterpret_cast<float4*>(out);
    const int total = N * 16;
    for (int i = t; i < total; i += gridDim.x * blockDim.x) {
        float4 h = o4[i];
        h.x = fmaf(h.x - am[0], w[0], b[0]);
        h.y = fmaf(h.y - am[1], w[1], b[1]);
        h.z = fmaf(h.z - am[2], w[2], b[2]);
        h.w = fmaf(h.w - am[3], w[3], b[3]);
        o4[i] = h;
    }
}

// ---------------------------------------------------------------------------
extern "C" void kernel_launch(void* const* d_in, const int* in_sizes, int n_in,
                              void* d_out, int out_size) {
    const float* x    = (const float*)d_in[0];
    const void*  ei   = d_in[1];
    const float* W0   = (const float*)d_in[2];
    const float* ln0w = (const float*)d_in[3];
    const float* ln0b = (const float*)d_in[4];
    const float* W1   = (const float*)d_in[5];
    const float* ln1w = (const float*)d_in[6];
    const float* ln1b = (const float*)d_in[7];
    const float* gnw  = (const float*)d_in[8];
    const float* gnb  = (const float*)d_in[9];
    const float* gna  = (const float*)d_in[10];

    const int N = in_sizes[0] / CH;
    const int E = in_sizes[1] / 2;
    float* out = (float*)d_out;

    k_detect<<<1, 64>>>((const int*)ei, E);                 // launch 1
    k_zero<<<(N + 255) / 256, 256>>>(N);                    // launch 2
    k_bucket<<<(E + 255) / 256, 256>>>(ei, E);              // launch 3

    const int ngroups = (N + 7) / 8;                        // warps needed
    const int mlp_blocks = (ngroups + 7) / 8;               // 8 warps per block
    k_mlp<<<mlp_blocks, 256>>>(x, W0, ln0w, ln0b,           // launch 4 (profiled)
                               W1, ln1w, ln1b, out, N);

    k_final<<<2048, 256>>>(gnw, gnb, gna, out, N);          // launch 5
}

// round 12
// speedup vs baseline: 1.0264x; 1.0264x over previous
#include <cuda_runtime.h>

#define CH 64
#define MAXN 65536
#define MAXDEG 64

// Scratch (no allocs allowed).
__device__ int   g_deg[MAXN];
__device__ int   g_bucket[(size_t)MAXN * MAXDEG];
__device__ float g_colsum[CH];
__device__ float g_sumsq[CH];
__device__ int   g_idx64;

#define FFMA2(acc, a, b) \
    asm("fma.rn.f32x2 %0, %1, %2, %0;" : "+l"(acc) : "l"(a), "l"(b))
#define PACK2(out, lo, hi) \
    asm("mov.b64 %0, {%1, %2};" : "=l"(out) : "f"(lo), "f"(hi))
#define UNPACK2(lo, hi, in) \
    asm("mov.b64 {%0, %1}, %2;" : "=f"(lo), "=f"(hi) : "l"(in))

// ---------------------------------------------------------------------------
// K1: zero degree counters + reduction buffers, detect index dtype.
// ---------------------------------------------------------------------------
__global__ void k_prep(const int* __restrict__ ei32, int N, int E) {
    int i = blockIdx.x * blockDim.x + threadIdx.x;
    if (i < N) g_deg[i] = 0;
    if (blockIdx.x == 0) {
        if (threadIdx.x < CH) { g_colsum[threadIdx.x] = 0.f; g_sumsq[threadIdx.x] = 0.f; }
        if (threadIdx.x == 0) {
            // int64 edge_index => high 32-bit word of every entry is 0.
            int allz = 1;
            int cnt = (E < 64) ? E : 64;
            for (int t = 0; t < cnt; t++) allz &= (ei32[2 * t + 1] == 0);
            g_idx64 = allz;
        }
    }
}

// ---------------------------------------------------------------------------
// K2: single-pass bucket scatter; slot = atomic return value.
// ---------------------------------------------------------------------------
__global__ void k_bucket(const void* __restrict__ ei, int E) {
    const int idx64 = g_idx64;
    const long long* e64 = (const long long*)ei;
    const int*       e32 = (const int*)ei;
    int i = blockIdx.x * blockDim.x + threadIdx.x;
    if (i < E) {
        int src, dst;
        if (idx64) { src = (int)e64[i]; dst = (int)e64[E + i]; }
        else       { src = e32[i];      dst = e32[E + i]; }
        int slot = atomicAdd(&g_deg[dst], 1);
        if (slot < MAXDEG)
            g_bucket[(size_t)dst * MAXDEG + slot] = src;
    }
}

// ---------------------------------------------------------------------------
// K3: dedicated gather — warp per row, tiny footprint, massive warp count so
// the 205MB L2 gather stream runs at LTS throughput, not exposed latency.
// agg written into `out` (k_mlp reads it back before overwriting).
// ---------------------------------------------------------------------------
__global__ void __launch_bounds__(256)
k_gather(const float* __restrict__ x, float* __restrict__ agg, int N) {
    const int lane = threadIdx.x & 31;
    const int row  = blockIdx.x * 8 + (threadIdx.x >> 5);
    if (row >= N) return;
    const float2* x2 = reinterpret_cast<const float2*>(x);
    int deg = g_deg[row];
    if (deg > MAXDEG) deg = MAXDEG;
    const int* nb = g_bucket + (size_t)row * MAXDEG;
    float2 acc0 = x2[row * 32 + lane];
    float2 acc1 = make_float2(0.f, 0.f);
    float2 acc2 = make_float2(0.f, 0.f);
    float2 acc3 = make_float2(0.f, 0.f);
    int j = 0;
    for (; j + 4 <= deg; j += 4) {
        int s0 = nb[j];
        int s1 = nb[j + 1];
        int s2 = nb[j + 2];
        int s3 = nb[j + 3];
        float2 v0 = x2[s0 * 32 + lane];
        float2 v1 = x2[s1 * 32 + lane];
        float2 v2 = x2[s2 * 32 + lane];
        float2 v3 = x2[s3 * 32 + lane];
        acc0.x += v0.x; acc0.y += v0.y;
        acc1.x += v1.x; acc1.y += v1.y;
        acc2.x += v2.x; acc2.y += v2.y;
        acc3.x += v3.x; acc3.y += v3.y;
    }
    for (; j < deg; j++) {
        int s0 = nb[j];
        float2 v0 = x2[s0 * 32 + lane];
        acc0.x += v0.x; acc0.y += v0.y;
    }
    acc0.x += acc1.x; acc0.y += acc1.y;
    acc2.x += acc3.x; acc2.y += acc3.y;
    acc0.x += acc2.x; acc0.y += acc2.y;
    reinterpret_cast<float2*>(agg)[row * 32 + lane] = acc0;
}

// ---------------------------------------------------------------------------
// Pair-packed 64x64 GEMM: h pairs pre-packed in smem (float2 per channel),
// hot loop = LDS + 8 weight-dup packs + 32 FFMA2 per kk (no h packs).
// ---------------------------------------------------------------------------
__device__ __forceinline__ void gemm64_pairs(
    const float4* __restrict__ wa, const float4* __restrict__ wb,
    const float2 (*__restrict__ hp)[CH], float* a0, float* a1) {
    unsigned long long pa[4][2];
    #pragma unroll
    for (int p = 0; p < 4; p++) { pa[p][0] = 0ull; pa[p][1] = 0ull; }
    #pragma unroll
    for (int kk = 0; kk < 16; kk++) {
        float4 va = wa[kk];
        float4 vb = wb[kk];
        unsigned long long wax, way, waz, waw, wbx, wby, wbz, wbw;
        PACK2(wax, va.x, va.x); PACK2(way, va.y, va.y);
        PACK2(waz, va.z, va.z); PACK2(waw, va.w, va.w);
        PACK2(wbx, vb.x, vb.x); PACK2(wby, vb.y, vb.y);
        PACK2(wbz, vb.z, vb.z); PACK2(wbw, vb.w, vb.w);
        #pragma unroll
        for (int p = 0; p < 4; p++) {
            const ulonglong2* hq = reinterpret_cast<const ulonglong2*>(hp[p]);
            ulonglong2 q0 = hq[2 * kk];          // channels 4kk, 4kk+1 (paired)
            ulonglong2 q1 = hq[2 * kk + 1];      // channels 4kk+2, 4kk+3
            FFMA2(pa[p][0], q0.x, wax); FFMA2(pa[p][0], q0.y, way);
            FFMA2(pa[p][0], q1.x, waz); FFMA2(pa[p][0], q1.y, waw);
            FFMA2(pa[p][1], q0.x, wbx); FFMA2(pa[p][1], q0.y, wby);
            FFMA2(pa[p][1], q1.x, wbz); FFMA2(pa[p][1], q1.y, wbw);
        }
    }
    #pragma unroll
    for (int p = 0; p < 4; p++) {
        UNPACK2(a0[2 * p], a0[2 * p + 1], pa[p][0]);
        UNPACK2(a1[2 * p], a1[2 * p + 1], pa[p][1]);
    }
}

// ---------------------------------------------------------------------------
// K4: MLP only (gather unfused). Warp handles 8 rows; agg read coalesced
// from `out`, staged pair-packed, 2x (GEMM->LN->ReLU), GraphNorm partials.
// ---------------------------------------------------------------------------
__global__ void __launch_bounds__(256, 4)
k_mlp(const float* __restrict__ W0, const float* __restrict__ ln0w,
      const float* __restrict__ ln0b, const float* __restrict__ W1,
      const float* __restrict__ ln1w, const float* __restrict__ ln1b,
      float* __restrict__ out, int N) {
    __shared__ __align__(16) float sW0[CH][68];
    __shared__ __align__(16) float sW1[CH][68];
    __shared__ __align__(16) float2 hp[8][4][CH];   // [warp][pair][channel]
    __shared__ float bsum[CH];
    __shared__ float bss[CH];

    const int tid  = threadIdx.x;
    const int lane = tid & 31;
    const int warp = tid >> 5;

    for (int i = tid; i < CH * CH; i += blockDim.x) {
        sW0[i >> 6][i & 63] = W0[i];
        sW1[i >> 6][i & 63] = W1[i];
    }
    if (tid < CH) { bsum[tid] = 0.f; bss[tid] = 0.f; }
    #pragma unroll
    for (int p = 0; p < 4; p++) {
        hp[warp][p][lane]      = make_float2(0.f, 0.f);
        hp[warp][p][lane + 32] = make_float2(0.f, 0.f);
    }

    const float w0a = ln0w[lane], w0b = ln0w[lane + 32];
    const float b0a = ln0b[lane], b0b = ln0b[lane + 32];
    const float w1a = ln1w[lane], w1b = ln1w[lane + 32];
    const float b1a = ln1b[lane], b1b = ln1b[lane + 32];
    __syncthreads();

    const float4* wa0 = reinterpret_cast<const float4*>(&sW0[lane][0]);
    const float4* wb0 = reinterpret_cast<const float4*>(&sW0[lane + 32][0]);
    const float4* wa1 = reinterpret_cast<const float4*>(&sW1[lane][0]);
    const float4* wb1 = reinterpret_cast<const float4*>(&sW1[lane + 32][0]);
    const float2* o2  = reinterpret_cast<const float2*>(out);

    float cs0 = 0.f, cs1 = 0.f, ss0 = 0.f, ss1 = 0.f;

    const int base = (blockIdx.x * 8 + warp) * 8;

    // ---- load 8 agg rows (coalesced), stage pair-packed ----
    #pragma unroll
    for (int r = 0; r < 8; r++) {
        int row = base + r;
        if (row < N) {
            float2 h = o2[row * 32 + lane];
            float* hpf = reinterpret_cast<float*>(&hp[warp][r >> 1][0]);
            int half = r & 1;
            hpf[4 * lane + half]     = h.x;   // channel 2*lane
            hpf[4 * lane + 2 + half] = h.y;   // channel 2*lane+1
        }
    }
    __syncwarp();

    // ---- layer 0 GEMM ----
    float a0[8], a1[8];
    gemm64_pairs(wa0, wb0, hp[warp], a0, a1);
    __syncwarp();

    // ---- LayerNorm 0 + ReLU, restage pair-packed ----
    #pragma unroll
    for (int r = 0; r < 8; r++) {
        float s = a0[r] + a1[r];
        #pragma unroll
        for (int o = 16; o; o >>= 1) s += __shfl_xor_sync(0xffffffffu, s, o);
        float mu = s * (1.f / 64.f);
        float d0 = a0[r] - mu, d1 = a1[r] - mu;
        float q = d0 * d0 + d1 * d1;
        #pragma unroll
        for (int o = 16; o; o >>= 1) q += __shfl_xor_sync(0xffffffffu, q, o);
        float inv = rsqrtf(q * (1.f / 64.f) + 1e-5f);
        float* hpf = reinterpret_cast<float*>(&hp[warp][r >> 1][0]);
        int half = r & 1;
        hpf[2 * lane + half]        = fmaxf(fmaf(d0 * inv, w0a, b0a), 0.f);
        hpf[2 * (lane + 32) + half] = fmaxf(fmaf(d1 * inv, w0b, b0b), 0.f);
    }
    __syncwarp();

    // ---- layer 1 GEMM ----
    gemm64_pairs(wa1, wb1, hp[warp], a0, a1);

    // ---- LayerNorm 1 + ReLU + store + GraphNorm partials ----
    #pragma unroll
    for (int r = 0; r < 8; r++) {
        int row = base + r;
        float s = a0[r] + a1[r];
        #pragma unroll
        for (int o = 16; o; o >>= 1) s += __shfl_xor_sync(0xffffffffu, s, o);
        float mu = s * (1.f / 64.f);
        float d0 = a0[r] - mu, d1 = a1[r] - mu;
        float q = d0 * d0 + d1 * d1;
        #pragma unroll
        for (int o = 16; o; o >>= 1) q += __shfl_xor_sync(0xffffffffu, q, o);
        float inv = rsqrtf(q * (1.f / 64.f) + 1e-5f);
        float v0 = fmaxf(fmaf(d0 * inv, w1a, b1a), 0.f);
        float v1 = fmaxf(fmaf(d1 * inv, w1b, b1b), 0.f);
        if (row < N) {
            float* orow = out + (size_t)row * CH;
            orow[lane]      = v0;
            orow[lane + 32] = v1;
            cs0 += v0; cs1 += v1;
            ss0 = fmaf(v0, v0, ss0);
            ss1 = fmaf(v1, v1, ss1);
        }
    }
    __syncwarp();

    // column sum / sumsq partials: register -> shared -> 128 global atomics.
    atomicAdd(&bsum[lane], cs0);
    atomicAdd(&bsum[lane + 32], cs1);
    atomicAdd(&bss[lane], ss0);
    atomicAdd(&bss[lane + 32], ss1);
    __syncthreads();
    if (tid < CH) {
        atomicAdd(&g_colsum[tid], bsum[tid]);
        atomicAdd(&g_sumsq[tid],  bss[tid]);
    }
}

// ---------------------------------------------------------------------------
// K5: final GraphNorm, in-place, float4. var = E[h^2] - 2*am*mu + am^2.
// ---------------------------------------------------------------------------
__global__ void k_final(const float* __restrict__ gnw, const float* __restrict__ gnb,
                        const float* __restrict__ gna, float* __restrict__ out,
                        int N) {
    const float invN = 1.f / (float)N;
    const int t = blockIdx.x * blockDim.x + threadIdx.x;
    const int c0 = (t & 15) * 4;
    float am[4], w[4], b[4];
    #pragma unroll
    for (int j = 0; j < 4; j++) {
        int c = c0 + j;
        float mu  = g_colsum[c] * invN;
        float a   = gna[c] * mu;
        float ex2 = g_sumsq[c] * invN;
        float var = ex2 - 2.f * a * mu + a * a;
        am[j] = a;
        w[j]  = gnw[c] * rsqrtf(var + 1e-5f);
        b[j]  = gnb[c];
    }
    float4* o4 = reinterpret_cast<float4*>(out);
    const int total = N * 16;
    for (int i = t; i < total; i += gridDim.x * blockDim.x) {
        float4 h = o4[i];
        h.x = fmaf(h.x - am[0], w[0], b[0]);
        h.y = fmaf(h.y - am[1], w[1], b[1]);
        h.z = fmaf(h.z - am[2], w[2], b[2]);
        h.w = fmaf(h.w - am[3], w[3], b[3]);
        o4[i] = h;
    }
}

// ---------------------------------------------------------------------------
extern "C" void kernel_launch(void* const* d_in, const int* in_sizes, int n_in,
                              void* d_out, int out_size) {
    const float* x    = (const float*)d_in[0];
    const void*  ei   = d_in[1];
    const float* W0   = (const float*)d_in[2];
    const float* ln0w = (const float*)d_in[3];
    const float* ln0b = (const float*)d_in[4];
    const float* W1   = (const float*)d_in[5];
    const float* ln1w = (const float*)d_in[6];
    const float* ln1b = (const float*)d_in[7];
    const float* gnw  = (const float*)d_in[8];
    const float* gnb  = (const float*)d_in[9];
    const float* gna  = (const float*)d_in[10];

    const int N = in_sizes[0] / CH;
    const int E = in_sizes[1] / 2;
    float* out = (float*)d_out;

    k_prep<<<(N + 255) / 256, 256>>>((const int*)ei, N, E);   // launch 1
    k_bucket<<<(E + 255) / 256, 256>>>(ei, E);                // launch 2
    k_gather<<<(N + 7) / 8, 256>>>(x, out, N);                // launch 3

    const int ngroups = (N + 7) / 8;                          // warps needed
    const int mlp_blocks = (ngroups + 7) / 8;                 // 8 warps/block
    k_mlp<<<mlp_blocks, 256>>>(W0, ln0w, ln0b,                // launch 4 (profiled)
                               W1, ln1w, ln1b, out, N);

    k_final<<<2048, 256>>>(gnw, gnb, gna, out, N);            // launch 5
}

// round 13
// speedup vs baseline: 1.0809x; 1.0530x over previous
#include <cuda_runtime.h>

#define CH 64
#define MAXN 65536
#define MAXDEG 64

// Scratch (no allocs allowed).
__device__ int   g_deg[MAXN];
__device__ int   g_bucket[(size_t)MAXN * MAXDEG];
__device__ float g_colsum[CH];
__device__ float g_sumsq[CH];
__device__ int   g_idx64;

#define FFMA2(acc, a, b) \
    asm("fma.rn.f32x2 %0, %1, %2, %0;" : "+l"(acc) : "l"(a), "l"(b))
#define PACK2(out, lo, hi) \
    asm("mov.b64 %0, {%1, %2};" : "=l"(out) : "f"(lo), "f"(hi))
#define UNPACK2(lo, hi, in) \
    asm("mov.b64 {%0, %1}, %2;" : "=f"(lo), "=f"(hi) : "l"(in))

// ---------------------------------------------------------------------------
// K1: zero degree counters + reduction buffers, detect index dtype.
// ---------------------------------------------------------------------------
__global__ void k_prep(const int* __restrict__ ei32, int N, int E) {
    int i = blockIdx.x * blockDim.x + threadIdx.x;
    if (i < N) g_deg[i] = 0;
    if (blockIdx.x == 0) {
        if (threadIdx.x < CH) { g_colsum[threadIdx.x] = 0.f; g_sumsq[threadIdx.x] = 0.f; }
        if (threadIdx.x == 0) {
            // int64 edge_index => high 32-bit word of every entry is 0.
            int allz = 1;
            int cnt = (E < 64) ? E : 64;
            for (int t = 0; t < cnt; t++) allz &= (ei32[2 * t + 1] == 0);
            g_idx64 = allz;
        }
    }
}

// ---------------------------------------------------------------------------
// K2: single-pass bucket scatter; slot = atomic return value.
// ---------------------------------------------------------------------------
__global__ void k_bucket(const void* __restrict__ ei, int E) {
    const int idx64 = g_idx64;
    const long long* e64 = (const long long*)ei;
    const int*       e32 = (const int*)ei;
    int i = blockIdx.x * blockDim.x + threadIdx.x;
    if (i < E) {
        int src, dst;
        if (idx64) { src = (int)e64[i]; dst = (int)e64[E + i]; }
        else       { src = e32[i];      dst = e32[E + i]; }
        int slot = atomicAdd(&g_deg[dst], 1);
        if (slot < MAXDEG)
            g_bucket[(size_t)dst * MAXDEG + slot] = src;
    }
}

// ---------------------------------------------------------------------------
// K3: dedicated gather — warp per row, tiny footprint, massive warp count so
// the 205MB L2 gather stream runs at LTS throughput, not exposed latency.
// agg written into `out` (k_mlp reads it back before overwriting).
// ---------------------------------------------------------------------------
__global__ void __launch_bounds__(256)
k_gather(const float* __restrict__ x, float* __restrict__ agg, int N) {
    const int lane = threadIdx.x & 31;
    const int row  = blockIdx.x * 8 + (threadIdx.x >> 5);
    if (row >= N) return;
    const float2* x2 = reinterpret_cast<const float2*>(x);
    int deg = g_deg[row];
    if (deg > MAXDEG) deg = MAXDEG;
    const int* nb = g_bucket + (size_t)row * MAXDEG;
    float2 acc0 = x2[row * 32 + lane];
    float2 acc1 = make_float2(0.f, 0.f);
    float2 acc2 = make_float2(0.f, 0.f);
    float2 acc3 = make_float2(0.f, 0.f);
    int j = 0;
    for (; j + 4 <= deg; j += 4) {
        int s0 = nb[j];
        int s1 = nb[j + 1];
        int s2 = nb[j + 2];
        int s3 = nb[j + 3];
        float2 v0 = x2[s0 * 32 + lane];
        float2 v1 = x2[s1 * 32 + lane];
        float2 v2 = x2[s2 * 32 + lane];
        float2 v3 = x2[s3 * 32 + lane];
        acc0.x += v0.x; acc0.y += v0.y;
        acc1.x += v1.x; acc1.y += v1.y;
        acc2.x += v2.x; acc2.y += v2.y;
        acc3.x += v3.x; acc3.y += v3.y;
    }
    for (; j < deg; j++) {
        int s0 = nb[j];
        float2 v0 = x2[s0 * 32 + lane];
        acc0.x += v0.x; acc0.y += v0.y;
    }
    acc0.x += acc1.x; acc0.y += acc1.y;
    acc2.x += acc3.x; acc2.y += acc3.y;
    acc0.x += acc2.x; acc0.y += acc2.y;
    reinterpret_cast<float2*>(agg)[row * 32 + lane] = acc0;
}

// ---------------------------------------------------------------------------
// Pair-packed 64x64 GEMM over 8 row-pairs (16 rows): hp reads are uniform
// (broadcast, ~free on the crossbar); weight LDS.128 traffic amortized over
// 16 rows instead of 8.
// ---------------------------------------------------------------------------
__device__ __forceinline__ void gemm64_pairs16(
    const float4* __restrict__ wa, const float4* __restrict__ wb,
    const float2 (*__restrict__ hp)[CH], float* a0, float* a1) {
    unsigned long long pa[8][2];
    #pragma unroll
    for (int p = 0; p < 8; p++) { pa[p][0] = 0ull; pa[p][1] = 0ull; }
    #pragma unroll
    for (int kk = 0; kk < 16; kk++) {
        float4 va = wa[kk];
        float4 vb = wb[kk];
        unsigned long long wax, way, waz, waw, wbx, wby, wbz, wbw;
        PACK2(wax, va.x, va.x); PACK2(way, va.y, va.y);
        PACK2(waz, va.z, va.z); PACK2(waw, va.w, va.w);
        PACK2(wbx, vb.x, vb.x); PACK2(wby, vb.y, vb.y);
        PACK2(wbz, vb.z, vb.z); PACK2(wbw, vb.w, vb.w);
        #pragma unroll
        for (int p = 0; p < 8; p++) {
            const ulonglong2* hq = reinterpret_cast<const ulonglong2*>(hp[p]);
            ulonglong2 q0 = hq[2 * kk];          // channels 4kk, 4kk+1 (paired)
            ulonglong2 q1 = hq[2 * kk + 1];      // channels 4kk+2, 4kk+3
            FFMA2(pa[p][0], q0.x, wax); FFMA2(pa[p][0], q0.y, way);
            FFMA2(pa[p][0], q1.x, waz); FFMA2(pa[p][0], q1.y, waw);
            FFMA2(pa[p][1], q0.x, wbx); FFMA2(pa[p][1], q0.y, wby);
            FFMA2(pa[p][1], q1.x, wbz); FFMA2(pa[p][1], q1.y, wbw);
        }
    }
    #pragma unroll
    for (int p = 0; p < 8; p++) {
        UNPACK2(a0[2 * p], a0[2 * p + 1], pa[p][0]);
        UNPACK2(a1[2 * p], a1[2 * p + 1], pa[p][1]);
    }
}

// ---------------------------------------------------------------------------
// K4: MLP only (gather unfused). Warp handles 16 rows (8 pairs); agg read
// coalesced from `out`, staged pair-packed, 2x (GEMM->LN->ReLU),
// GraphNorm partials. launch_bounds(256,3): reg cap 85, smem 68KB x3 fits.
// ---------------------------------------------------------------------------
__global__ void __launch_bounds__(256, 3)
k_mlp(const float* __restrict__ W0, const float* __restrict__ ln0w,
      const float* __restrict__ ln0b, const float* __restrict__ W1,
      const float* __restrict__ ln1w, const float* __restrict__ ln1b,
      float* __restrict__ out, int N) {
    __shared__ __align__(16) float sW0[CH][68];
    __shared__ __align__(16) float sW1[CH][68];
    __shared__ __align__(16) float2 hp[8][8][CH];   // [warp][pair][channel]
    __shared__ float bsum[CH];
    __shared__ float bss[CH];

    const int tid  = threadIdx.x;
    const int lane = tid & 31;
    const int warp = tid >> 5;

    for (int i = tid; i < CH * CH; i += blockDim.x) {
        sW0[i >> 6][i & 63] = W0[i];
        sW1[i >> 6][i & 63] = W1[i];
    }
    if (tid < CH) { bsum[tid] = 0.f; bss[tid] = 0.f; }
    #pragma unroll
    for (int p = 0; p < 8; p++) {
        hp[warp][p][lane]      = make_float2(0.f, 0.f);
        hp[warp][p][lane + 32] = make_float2(0.f, 0.f);
    }

    const float w0a = ln0w[lane], w0b = ln0w[lane + 32];
    const float b0a = ln0b[lane], b0b = ln0b[lane + 32];
    const float w1a = ln1w[lane], w1b = ln1w[lane + 32];
    const float b1a = ln1b[lane], b1b = ln1b[lane + 32];
    __syncthreads();

    const float4* wa0 = reinterpret_cast<const float4*>(&sW0[lane][0]);
    const float4* wb0 = reinterpret_cast<const float4*>(&sW0[lane + 32][0]);
    const float4* wa1 = reinterpret_cast<const float4*>(&sW1[lane][0]);
    const float4* wb1 = reinterpret_cast<const float4*>(&sW1[lane + 32][0]);
    const float2* o2  = reinterpret_cast<const float2*>(out);

    float cs0 = 0.f, cs1 = 0.f, ss0 = 0.f, ss1 = 0.f;

    const int base = (blockIdx.x * 8 + warp) * 16;

    // ---- load 16 agg rows (coalesced), stage pair-packed ----
    #pragma unroll
    for (int r = 0; r < 16; r++) {
        int row = base + r;
        if (row < N) {
            float2 h = o2[row * 32 + lane];
            float* hpf = reinterpret_cast<float*>(&hp[warp][r >> 1][0]);
            int half = r & 1;
            hpf[4 * lane + half]     = h.x;   // channel 2*lane
            hpf[4 * lane + 2 + half] = h.y;   // channel 2*lane+1
        }
    }
    __syncwarp();

    // ---- layer 0 GEMM ----
    float a0[16], a1[16];
    gemm64_pairs16(wa0, wb0, hp[warp], a0, a1);
    __syncwarp();

    // ---- LayerNorm 0 + ReLU, restage pair-packed ----
    #pragma unroll
    for (int r = 0; r < 16; r++) {
        float s = a0[r] + a1[r];
        #pragma unroll
        for (int o = 16; o; o >>= 1) s += __shfl_xor_sync(0xffffffffu, s, o);
        float mu = s * (1.f / 64.f);
        float d0 = a0[r] - mu, d1 = a1[r] - mu;
        float q = d0 * d0 + d1 * d1;
        #pragma unroll
        for (int o = 16; o; o >>= 1) q += __shfl_xor_sync(0xffffffffu, q, o);
        float inv = rsqrtf(q * (1.f / 64.f) + 1e-5f);
        float* hpf = reinterpret_cast<float*>(&hp[warp][r >> 1][0]);
        int half = r & 1;
        hpf[2 * lane + half]        = fmaxf(fmaf(d0 * inv, w0a, b0a), 0.f);
        hpf[2 * (lane + 32) + half] = fmaxf(fmaf(d1 * inv, w0b, b0b), 0.f);
    }
    __syncwarp();

    // ---- layer 1 GEMM ----
    gemm64_pairs16(wa1, wb1, hp[warp], a0, a1);

    // ---- LayerNorm 1 + ReLU + store + GraphNorm partials ----
    #pragma unroll
    for (int r = 0; r < 16; r++) {
        int row = base + r;
        float s = a0[r] + a1[r];
        #pragma unroll
        for (int o = 16; o; o >>= 1) s += __shfl_xor_sync(0xffffffffu, s, o);
        float mu = s * (1.f / 64.f);
        float d0 = a0[r] - mu, d1 = a1[r] - mu;
        float q = d0 * d0 + d1 * d1;
        #pragma unroll
        for (int o = 16; o; o >>= 1) q += __shfl_xor_sync(0xffffffffu, q, o);
        float inv = rsqrtf(q * (1.f / 64.f) + 1e-5f);
        float v0 = fmaxf(fmaf(d0 * inv, w1a, b1a), 0.f);
        float v1 = fmaxf(fmaf(d1 * inv, w1b, b1b), 0.f);
        if (row < N) {
            float* orow = out + (size_t)row * CH;
            orow[lane]      = v0;
            orow[lane + 32] = v1;
            cs0 += v0; cs1 += v1;
            ss0 = fmaf(v0, v0, ss0);
            ss1 = fmaf(v1, v1, ss1);
        }
    }
    __syncwarp();

    // column sum / sumsq partials: register -> shared -> 128 global atomics.
    atomicAdd(&bsum[lane], cs0);
    atomicAdd(&bsum[lane + 32], cs1);
    atomicAdd(&bss[lane], ss0);
    atomicAdd(&bss[lane + 32], ss1);
    __syncthreads();
    if (tid < CH) {
        atomicAdd(&g_colsum[tid], bsum[tid]);
        atomicAdd(&g_sumsq[tid],  bss[tid]);
    }
}

// ---------------------------------------------------------------------------
// K5: final GraphNorm, in-place, float4. var = E[h^2] - 2*am*mu + am^2.
// ---------------------------------------------------------------------------
__global__ void k_final(const float* __restrict__ gnw, const float* __restrict__ gnb,
                        const float* __restrict__ gna, float* __restrict__ out,
                        int N) {
    const float invN = 1.f / (float)N;
    const int t = blockIdx.x * blockDim.x + threadIdx.x;
    const int c0 = (t & 15) * 4;
    float am[4], w[4], b[4];
    #pragma unroll
    for (int j = 0; j < 4; j++) {
        int c = c0 + j;
        float mu  = g_colsum[c] * invN;
        float a   = gna[c] * mu;
        float ex2 = g_sumsq[c] * invN;
        float var = ex2 - 2.f * a * mu + a * a;
        am[j] = a;
        w[j]  = gnw[c] * rsqrtf(var + 1e-5f);
        b[j]  = gnb[c];
    }
    float4* o4 = reinterpret_cast<float4*>(out);
    const int total = N * 16;
    for (int i = t; i < total; i += gridDim.x * blockDim.x) {
        float4 h = o4[i];
        h.x = fmaf(h.x - am[0], w[0], b[0]);
        h.y = fmaf(h.y - am[1], w[1], b[1]);
        h.z = fmaf(h.z - am[2], w[2], b[2]);
        h.w = fmaf(h.w - am[3], w[3], b[3]);
        o4[i] = h;
    }
}

// ---------------------------------------------------------------------------
extern "C" void kernel_launch(void* const* d_in, const int* in_sizes, int n_in,
                              void* d_out, int out_size) {
    const float* x    = (const float*)d_in[0];
    const void*  ei   = d_in[1];
    const float* W0   = (const float*)d_in[2];
    const float* ln0w = (const float*)d_in[3];
    const float* ln0b = (const float*)d_in[4];
    const float* W1   = (const float*)d_in[5];
    const float* ln1w = (const float*)d_in[6];
    const float* ln1b = (const float*)d_in[7];
    const float* gnw  = (const float*)d_in[8];
    const float* gnb  = (const float*)d_in[9];
    const float* gna  = (const float*)d_in[10];

    const int N = in_sizes[0] / CH;
    const int E = in_sizes[1] / 2;
    float* out = (float*)d_out;

    k_prep<<<(N + 255) / 256, 256>>>((const int*)ei, N, E);   // launch 1
    k_bucket<<<(E + 255) / 256, 256>>>(ei, E);                // launch 2
    k_gather<<<(N + 7) / 8, 256>>>(x, out, N);                // launch 3

    const int ngroups = (N + 15) / 16;                        // warps needed
    const int mlp_blocks = (ngroups + 7) / 8;                 // 8 warps/block
    k_mlp<<<mlp_blocks, 256>>>(W0, ln0w, ln0b,                // launch 4 (profiled)
                               W1, ln1w, ln1b, out, N);

    k_final<<<2048, 256>>>(gnw, gnb, gna, out, N);            // launch 5
}